// round 9
// baseline (speedup 1.0000x reference)
#include <cuda_runtime.h>
#include <math.h>
#include <stdint.h>

#define N_NODES 50000
#define N_EDGES 800000
#define F 128
#define NF (N_NODES * F)
#define GSZ (256 * 128)   // one gate weight matrix [2F, F]

// ---------------- static device scratch (no allocs allowed) ----------------
__device__ float g_S1[N_NODES * 256];
__device__ float g_Yn1[N_NODES * 256];
__device__ float g_AGG1[N_NODES * 256];
__device__ float g_S2[N_NODES * 128];
__device__ float g_Yn2[N_NODES * 128];
__device__ float g_AGG2[N_NODES * 128];
__device__ float g_RH[N_NODES * 128];
__device__ float g_U[N_NODES * 128];
__device__ float g_WT[12 * GSZ];        // transposed tf32-rounded weights [128n x 256k]
// CSR scratch
__device__ int   g_deg[N_NODES];
__device__ int   g_rowstart[N_NODES + 1];
__device__ int   g_cursor[N_NODES];
__device__ int   g_ssrc[N_EDGES];
__device__ float g_sew[N_EDGES];

// ---------------- helpers ----------------
__device__ __forceinline__ float sigmoidf_(float x) { return 1.0f / (1.0f + expf(-x)); }

__device__ __forceinline__ uint32_t smem_u32(const void* p) {
    uint32_t a;
    asm("{ .reg .u64 t; cvta.to.shared.u64 t, %1; cvt.u32.u64 %0, t; }" : "=r"(a) : "l"(p));
    return a;
}
__device__ __forceinline__ uint32_t to_tf32(float x) {
    uint32_t r;
    asm("cvt.rna.tf32.f32 %0, %1;" : "=r"(r) : "f"(x));
    return r;
}
__device__ __forceinline__ void cp16(uint32_t dst, const void* src, int srcsz) {
    asm volatile("cp.async.cg.shared.global [%0], [%1], 16, %2;"
                 :: "r"(dst), "l"(src), "r"(srcsz) : "memory");
}
#define CP_COMMIT() asm volatile("cp.async.commit_group;" ::: "memory")
#define CP_WAIT(n)  asm volatile("cp.async.wait_group %0;" :: "n"(n) : "memory")

__device__ __forceinline__ void mma_tf32(float& d0, float& d1, float& d2, float& d3,
                                         uint32_t a0, uint32_t a1, uint32_t a2, uint32_t a3,
                                         uint32_t b0, uint32_t b1) {
    asm volatile("mma.sync.aligned.m16n8k8.row.col.f32.tf32.tf32.f32 "
                 "{%0,%1,%2,%3}, {%4,%5,%6,%7}, {%8,%9}, {%0,%1,%2,%3};"
                 : "+f"(d0), "+f"(d1), "+f"(d2), "+f"(d3)
                 : "r"(a0), "r"(a1), "r"(a2), "r"(a3), "r"(b0), "r"(b1));
}

// ---------------- CSR build ----------------
__global__ void zero_int(int* __restrict__ p, int n) {
    int i = blockIdx.x * blockDim.x + threadIdx.x;
    if (i < n) p[i] = 0;
}
__global__ void hist_dst(const int* __restrict__ dst, int* __restrict__ deg) {
    int e = blockIdx.x * blockDim.x + threadIdx.x;
    if (e < N_EDGES) atomicAdd(&deg[dst[e]], 1);
}
// single-block exclusive scan over 50000 -> row_start + cursor copy
__global__ void scan50k(const int* __restrict__ deg, int* __restrict__ row_start,
                        int* __restrict__ cursor) {
    __shared__ int warp_sums[32];
    __shared__ int carry_s;
    int tid = threadIdx.x;
    if (tid == 0) carry_s = 0;
    __syncthreads();
    for (int base = 0; base < N_NODES; base += 1024) {
        int i = base + tid;
        int v = (i < N_NODES) ? deg[i] : 0;
        int x = v;
#pragma unroll
        for (int o = 1; o < 32; o <<= 1) {
            int y = __shfl_up_sync(0xFFFFFFFFu, x, o);
            if ((tid & 31) >= o) x += y;
        }
        if ((tid & 31) == 31) warp_sums[tid >> 5] = x;
        __syncthreads();
        if (tid < 32) {
            int s = warp_sums[tid];
            int t = s;
#pragma unroll
            for (int o = 1; o < 32; o <<= 1) {
                int y = __shfl_up_sync(0xFFFFFFFFu, t, o);
                if (tid >= o) t += y;
            }
            warp_sums[tid] = t - s;   // exclusive warp offset
        }
        __syncthreads();
        int incl = x + warp_sums[tid >> 5] + carry_s;
        if (i < N_NODES) { row_start[i] = incl - v; cursor[i] = incl - v; }
        __syncthreads();
        if (tid == 1023) carry_s = incl;
        __syncthreads();
    }
    if (tid == 0) row_start[N_NODES] = carry_s;
}
__global__ void scatter_edges(const int* __restrict__ src, const int* __restrict__ dst,
                              const float* __restrict__ ew, int* __restrict__ cursor,
                              int* __restrict__ ssrc, float* __restrict__ sew) {
    int e = blockIdx.x * blockDim.x + threadIdx.x;
    if (e >= N_EDGES) return;
    int d = dst[e];
    int p = atomicAdd(&cursor[d], 1);
    ssrc[p] = src[e];
    sew[p] = ew[e];
}

// ---------------- CSR aggregation: agg[v] = sum_{e in row v} w_e * Yn[src_e] ----------------
// warp per node; overwrites agg (no pre-zero needed)
template <int C>
__global__ void __launch_bounds__(256) csr_agg(
    const int* __restrict__ row_start, const int* __restrict__ ssrc,
    const float* __restrict__ sew, const float* __restrict__ Yn, float* __restrict__ agg)
{
    int node = (blockIdx.x * blockDim.x + threadIdx.x) >> 5;
    if (node >= N_NODES) return;
    int lane = threadIdx.x & 31;
    int p0 = row_start[node], p1 = row_start[node + 1];
    float4 acc[C / 128];
#pragma unroll
    for (int c = 0; c < C / 128; c++) acc[c] = make_float4(0.f, 0.f, 0.f, 0.f);

    int p = p0;
    for (; p + 1 < p1; p += 2) {
        int s0 = __ldg(&ssrc[p]),     s1 = __ldg(&ssrc[p + 1]);
        float w0 = __ldg(&sew[p]),    w1 = __ldg(&sew[p + 1]);
        const float4* y0 = (const float4*)(Yn + (size_t)s0 * C);
        const float4* y1 = (const float4*)(Yn + (size_t)s1 * C);
#pragma unroll
        for (int c = 0; c < C / 128; c++) {
            float4 v0 = __ldg(&y0[c * 32 + lane]);
            float4 v1 = __ldg(&y1[c * 32 + lane]);
            acc[c].x += w0 * v0.x + w1 * v1.x;
            acc[c].y += w0 * v0.y + w1 * v1.y;
            acc[c].z += w0 * v0.z + w1 * v1.z;
            acc[c].w += w0 * v0.w + w1 * v1.w;
        }
    }
    if (p < p1) {
        int s0 = __ldg(&ssrc[p]);
        float w0 = __ldg(&sew[p]);
        const float4* y0 = (const float4*)(Yn + (size_t)s0 * C);
#pragma unroll
        for (int c = 0; c < C / 128; c++) {
            float4 v0 = __ldg(&y0[c * 32 + lane]);
            acc[c].x += w0 * v0.x; acc[c].y += w0 * v0.y;
            acc[c].z += w0 * v0.z; acc[c].w += w0 * v0.w;
        }
    }
    float4* ap = (float4*)(agg + (size_t)node * C);
#pragma unroll
    for (int c = 0; c < C / 128; c++) ap[c * 32 + lane] = acc[c];
}

// ---------------- weight transpose ----------------
__global__ void transpose_w(const float* __restrict__ Ws, const float* __restrict__ Wn,
                            float* __restrict__ WT) {
    int mat = blockIdx.y;                 // (l*2+sn)*3+g
    int l = mat / 6, sn = (mat / 3) & 1, g = mat % 3;
    const float* src = (sn ? Wn : Ws) + ((size_t)l * 3 + g) * GSZ;
    float* dst = WT + (size_t)mat * GSZ;
    int i = blockIdx.x * blockDim.x + threadIdx.x;
    if (i < GSZ) {
        int n = i >> 8; int k = i & 255;
        uint32_t t = to_tf32(src[k * 128 + n]);
        dst[i] = __uint_as_float(t);
    }
}

// ---------------- tensor-core GEMM via mma.sync tf32 ----------------
#define TSTR 36
#define TILE_B (128 * TSTR * 4)

__global__ void __launch_bounds__(256) gemm_tc(
    const float* __restrict__ A0, const float* __restrict__ A1,
    const float* __restrict__ BTself, const float* __restrict__ BTneigh,
    int half, float* __restrict__ Cself, float* __restrict__ Cneigh, int ldc)
{
    extern __shared__ float smem[];
    float* sA[2] = { smem,                smem + 128 * TSTR };
    float* sB[2] = { smem + 2 * 128 * TSTR, smem + 3 * 128 * TSTR };
    uint32_t uA[2] = { smem_u32(sA[0]), smem_u32(sA[1]) };
    uint32_t uB[2] = { smem_u32(sB[0]), smem_u32(sB[1]) };

    int tid = threadIdx.x, wid = tid >> 5, lid = tid & 31;
    int lr = lid >> 2, lc = lid & 3;
    int m0 = blockIdx.x * 128;
    int by = blockIdx.y;
    const float* BT; float* Cp; int colOff;
    if (by < half) { BT = BTself + (size_t)by * GSZ;           Cp = Cself;  colOff = by * 128; }
    else           { BT = BTneigh + (size_t)(by - half) * GSZ; Cp = Cneigh; colOff = (by - half) * 128; }

    int wm = wid & 1, wn = wid >> 1;

    float acc[4][4][4];
#pragma unroll
    for (int mt = 0; mt < 4; mt++)
#pragma unroll
        for (int nt = 0; nt < 4; nt++)
#pragma unroll
            for (int j = 0; j < 4; j++) acc[mt][nt][j] = 0.f;

    auto copy_tile = [&](int kt, int b) {
        const float* A = (kt < 4) ? A0 : A1;
        int kb = (kt & 3) * 32;
#pragma unroll
        for (int i = 0; i < 4; i++) {
            int c = tid + i * 256;
            int row = c >> 3, q = c & 7;
            int gr = m0 + row;
            int sz = (gr < N_NODES) ? 16 : 0;
            cp16(uA[b] + (uint32_t)(row * TSTR + q * 4) * 4,
                 A + (size_t)gr * 128 + kb + q * 4, sz);
            cp16(uB[b] + (uint32_t)(row * TSTR + q * 4) * 4,
                 BT + (size_t)row * 256 + kt * 32 + q * 4, 16);
        }
    };

    copy_tile(0, 0);
    CP_COMMIT();

    for (int kt = 0; kt < 8; kt++) {
        int b = kt & 1;
        if (kt < 7) { copy_tile(kt + 1, b ^ 1); CP_COMMIT(); CP_WAIT(1); }
        else        { CP_WAIT(0); }
        __syncthreads();

        const float* As = sA[b];
        const float* Bs = sB[b];
#pragma unroll
        for (int k8 = 0; k8 < 4; k8++) {
            int k0 = k8 * 8;
            uint32_t bf[4][2];
#pragma unroll
            for (int nt = 0; nt < 4; nt++) {
                int nb = 32 * wn + 8 * nt + lr;
                bf[nt][0] = __float_as_uint(Bs[nb * TSTR + k0 + lc]);
                bf[nt][1] = __float_as_uint(Bs[nb * TSTR + k0 + lc + 4]);
            }
#pragma unroll
            for (int mt = 0; mt < 4; mt++) {
                int rb = 64 * wm + 16 * mt;
                uint32_t a0 = to_tf32(As[(rb + lr) * TSTR + k0 + lc]);
                uint32_t a1 = to_tf32(As[(rb + 8 + lr) * TSTR + k0 + lc]);
                uint32_t a2 = to_tf32(As[(rb + lr) * TSTR + k0 + lc + 4]);
                uint32_t a3 = to_tf32(As[(rb + 8 + lr) * TSTR + k0 + lc + 4]);
#pragma unroll
                for (int nt = 0; nt < 4; nt++)
                    mma_tf32(acc[mt][nt][0], acc[mt][nt][1], acc[mt][nt][2], acc[mt][nt][3],
                             a0, a1, a2, a3, bf[nt][0], bf[nt][1]);
            }
        }
        __syncthreads();
    }

#pragma unroll
    for (int mt = 0; mt < 4; mt++) {
        int r0 = m0 + 64 * wm + 16 * mt + lr;
#pragma unroll
        for (int nt = 0; nt < 4; nt++) {
            int col = colOff + 32 * wn + 8 * nt + 2 * lc;
            if (r0 < N_NODES)
                *(float2*)(Cp + (size_t)r0 * ldc + col) =
                    make_float2(acc[mt][nt][0], acc[mt][nt][1]);
            if (r0 + 8 < N_NODES)
                *(float2*)(Cp + (size_t)(r0 + 8) * ldc + col) =
                    make_float2(acc[mt][nt][2], acc[mt][nt][3]);
        }
    }
}

// ---------------- gates ----------------
__global__ void gates_ru(const float* __restrict__ S1, const float* __restrict__ A1g,
                         const float* __restrict__ br, const float* __restrict__ bu,
                         const float* __restrict__ h,
                         float* __restrict__ RH, float* __restrict__ U)
{
    int idx = blockIdx.x * blockDim.x + threadIdx.x;
    if (idx >= NF) return;
    int i = idx >> 7;
    int f = idx & 127;
    float r = sigmoidf_(S1[(size_t)i * 256 + f] + A1g[(size_t)i * 256 + f] + __ldg(&br[f]));
    float u = sigmoidf_(S1[(size_t)i * 256 + 128 + f] + A1g[(size_t)i * 256 + 128 + f] + __ldg(&bu[f]));
    RH[idx] = r * h[idx];
    U[idx] = u;
}

__global__ void finalize(const float* __restrict__ S2, const float* __restrict__ A2g,
                         const float* __restrict__ bc,
                         const float* __restrict__ h, const float* __restrict__ U,
                         float* __restrict__ out_layer, float* __restrict__ out_extra)
{
    int idx = blockIdx.x * blockDim.x + threadIdx.x;
    if (idx >= NF) return;
    int f = idx & 127;
    float c = sigmoidf_(S2[idx] + A2g[idx] + __ldg(&bc[f]));
    float u = U[idx];
    float hn = u * h[idx] + (1.0f - u) * c;
    out_layer[idx] = hn;
    if (out_extra) out_extra[idx] = hn;
}

// ---------------- launch ----------------
extern "C" void kernel_launch(void* const* d_in, const int* in_sizes, int n_in,
                              void* d_out, int out_size)
{
    const float* x0   = (const float*)d_in[0];
    const float* hst  = (const float*)d_in[1];
    const int*   src  = (const int*)d_in[2];
    const int*   dst  = (const int*)d_in[3];
    const float* ew   = (const float*)d_in[4];
    const float* Ws   = (const float*)d_in[5];
    const float* Wn   = (const float*)d_in[6];
    const float* bias = (const float*)d_in[7];
    float* out = (float*)d_out;

    float *S1, *Yn1, *A1g, *S2, *Yn2, *A2g, *RH, *U, *WT, *SEW;
    int *DEG, *RS, *CUR, *SSRC;
    cudaGetSymbolAddress((void**)&S1,  g_S1);
    cudaGetSymbolAddress((void**)&Yn1, g_Yn1);
    cudaGetSymbolAddress((void**)&A1g, g_AGG1);
    cudaGetSymbolAddress((void**)&S2,  g_S2);
    cudaGetSymbolAddress((void**)&Yn2, g_Yn2);
    cudaGetSymbolAddress((void**)&A2g, g_AGG2);
    cudaGetSymbolAddress((void**)&RH,  g_RH);
    cudaGetSymbolAddress((void**)&U,   g_U);
    cudaGetSymbolAddress((void**)&WT,  g_WT);
    cudaGetSymbolAddress((void**)&DEG, g_deg);
    cudaGetSymbolAddress((void**)&RS,  g_rowstart);
    cudaGetSymbolAddress((void**)&CUR, g_cursor);
    cudaGetSymbolAddress((void**)&SSRC, g_ssrc);
    cudaGetSymbolAddress((void**)&SEW, g_sew);

    const int SMEM_SZ = 4 * TILE_B;
    cudaFuncSetAttribute(gemm_tc, cudaFuncAttributeMaxDynamicSharedMemorySize, SMEM_SZ);

    const int mtiles = (N_NODES + 127) / 128;
    const int agg_blocks = (N_NODES * 32 + 255) / 256;
    const int el_blocks = (NF + 255) / 256;
    const int eb = (N_EDGES + 255) / 256;

    // ---- CSR build (per launch) + weight transpose ----
    transpose_w<<<dim3((GSZ + 255) / 256, 12), 256>>>(Ws, Wn, WT);
    zero_int<<<(N_NODES + 255) / 256, 256>>>(DEG, N_NODES);
    hist_dst<<<eb, 256>>>(dst, DEG);
    scan50k<<<1, 1024>>>(DEG, RS, CUR);
    scatter_edges<<<eb, 256>>>(src, dst, ew, CUR, SSRC, SEW);

    for (int l = 0; l < 2; l++) {
        const float* xl = (l == 0) ? x0 : (out + NF);
        const float* hl = hst + (size_t)l * NF;
        const float* BTs = WT + (size_t)((l * 2 + 0) * 3) * GSZ;
        const float* BTn = WT + (size_t)((l * 2 + 1) * 3) * GSZ;
        const float* b_r = bias + ((size_t)l * 3 + 0) * 128;
        const float* b_u = bias + ((size_t)l * 3 + 1) * 128;
        const float* b_c = bias + ((size_t)l * 3 + 2) * 128;

        gemm_tc<<<dim3(mtiles, 4), 256, SMEM_SZ>>>(xl, hl, BTs, BTn, 2, S1, Yn1, 256);
        csr_agg<256><<<agg_blocks, 256>>>(RS, SSRC, SEW, Yn1, A1g);
        gates_ru<<<el_blocks, 256>>>(S1, A1g, b_r, b_u, hl, RH, U);

        gemm_tc<<<dim3(mtiles, 2), 256, SMEM_SZ>>>(xl, RH, BTs + 2 * GSZ, BTn + 2 * GSZ,
                                                   1, S2, Yn2, 128);
        csr_agg<128><<<agg_blocks, 256>>>(RS, SSRC, SEW, Yn2, A2g);

        float* out_layer = out + (size_t)(l + 1) * NF;
        float* out_extra = (l == 1) ? out : nullptr;
        finalize<<<el_blocks, 256>>>(S2, A2g, b_c, hl, U, out_layer, out_extra);
    }
    (void)in_sizes; (void)n_in; (void)out_size;
}

// round 12
// speedup vs baseline: 1.4789x; 1.4789x over previous
#include <cuda_runtime.h>
#include <math.h>
#include <stdint.h>

#define N_NODES 50000
#define N_EDGES 800000
#define F 128
#define NF (N_NODES * F)
#define GSZ (256 * 128)   // one gate weight matrix [2F, F]
#define SCAN_B 196        // ceil(50000/256)

// ---------------- static device scratch (no allocs allowed) ----------------
__device__ float g_S1[N_NODES * 256];
__device__ float g_Yn1[N_NODES * 256];
__device__ float g_AGG1[N_NODES * 256];
__device__ float g_S2[N_NODES * 128];
__device__ float g_Yn2[N_NODES * 128];
__device__ float g_AGG2[N_NODES * 128];
__device__ float g_RH[N_NODES * 128];
__device__ float g_U[N_NODES * 128];
__device__ float g_WT[12 * GSZ];        // transposed tf32-rounded weights [128n x 256k]
// CSR scratch
__device__ int   g_deg[N_NODES];
__device__ int   g_rowstart[N_NODES + 1];
__device__ int   g_cursor[N_NODES];
__device__ int   g_ssrc[N_EDGES];
__device__ float g_sew[N_EDGES];
__device__ int   g_bsum[SCAN_B];
__device__ int   g_boff[SCAN_B];

// ---------------- helpers ----------------
__device__ __forceinline__ float sigmoidf_(float x) { return 1.0f / (1.0f + expf(-x)); }

__device__ __forceinline__ uint32_t smem_u32(const void* p) {
    uint32_t a;
    asm("{ .reg .u64 t; cvta.to.shared.u64 t, %1; cvt.u32.u64 %0, t; }" : "=r"(a) : "l"(p));
    return a;
}
__device__ __forceinline__ uint32_t to_tf32(float x) {
    uint32_t r;
    asm("cvt.rna.tf32.f32 %0, %1;" : "=r"(r) : "f"(x));
    return r;
}
__device__ __forceinline__ void cp16(uint32_t dst, const void* src, int srcsz) {
    asm volatile("cp.async.cg.shared.global [%0], [%1], 16, %2;"
                 :: "r"(dst), "l"(src), "r"(srcsz) : "memory");
}
#define CP_COMMIT() asm volatile("cp.async.commit_group;" ::: "memory")
#define CP_WAIT(n)  asm volatile("cp.async.wait_group %0;" :: "n"(n) : "memory")

__device__ __forceinline__ void mma_tf32(float& d0, float& d1, float& d2, float& d3,
                                         uint32_t a0, uint32_t a1, uint32_t a2, uint32_t a3,
                                         uint32_t b0, uint32_t b1) {
    asm volatile("mma.sync.aligned.m16n8k8.row.col.f32.tf32.tf32.f32 "
                 "{%0,%1,%2,%3}, {%4,%5,%6,%7}, {%8,%9}, {%0,%1,%2,%3};"
                 : "+f"(d0), "+f"(d1), "+f"(d2), "+f"(d3)
                 : "r"(a0), "r"(a1), "r"(a2), "r"(a3), "r"(b0), "r"(b1));
}

// ---------------- CSR build ----------------
__global__ void zero_int(int* __restrict__ p, int n) {
    int i = blockIdx.x * blockDim.x + threadIdx.x;
    if (i < n) p[i] = 0;
}
__global__ void hist_dst(const int* __restrict__ dst, int* __restrict__ deg) {
    int e = blockIdx.x * blockDim.x + threadIdx.x;
    if (e < N_EDGES) atomicAdd(&deg[dst[e]], 1);
}
// scan step 1: per-block sums of 256 deg entries
__global__ void scan_bsum(const int* __restrict__ deg, int* __restrict__ bsum) {
    __shared__ int ws[8];
    int i = blockIdx.x * 256 + threadIdx.x;
    int v = (i < N_NODES) ? deg[i] : 0;
#pragma unroll
    for (int o = 16; o > 0; o >>= 1) v += __shfl_down_sync(0xFFFFFFFFu, v, o);
    if ((threadIdx.x & 31) == 0) ws[threadIdx.x >> 5] = v;
    __syncthreads();
    if (threadIdx.x < 8) {
        int s = ws[threadIdx.x];
#pragma unroll
        for (int o = 4; o > 0; o >>= 1) s += __shfl_down_sync(0xFFu, s, o);
        if (threadIdx.x == 0) bsum[blockIdx.x] = s;
    }
}
// scan step 2: exclusive scan of SCAN_B partials (1 block, Hillis-Steele in smem)
__global__ void scan_boff(const int* __restrict__ bsum, int* __restrict__ boff,
                          int* __restrict__ row_start) {
    __shared__ int s[256];
    int t = threadIdx.x;
    int v = (t < SCAN_B) ? bsum[t] : 0;
    s[t] = v;
    __syncthreads();
#pragma unroll
    for (int o = 1; o < 256; o <<= 1) {
        int y = (t >= o) ? s[t - o] : 0;
        __syncthreads();
        s[t] += y;
        __syncthreads();
    }
    if (t < SCAN_B) boff[t] = s[t] - v;
    if (t == 255) row_start[N_NODES] = s[255];
}
// scan step 3: in-block exclusive scan + block offset -> row_start, cursor
__global__ void scan_apply(const int* __restrict__ deg, const int* __restrict__ boff,
                           int* __restrict__ row_start, int* __restrict__ cursor) {
    __shared__ int ws[8];
    int t = threadIdx.x;
    int i = blockIdx.x * 256 + t;
    int v = (i < N_NODES) ? deg[i] : 0;
    int x = v;
#pragma unroll
    for (int o = 1; o < 32; o <<= 1) {
        int y = __shfl_up_sync(0xFFFFFFFFu, x, o);
        if ((t & 31) >= o) x += y;
    }
    if ((t & 31) == 31) ws[t >> 5] = x;
    __syncthreads();
    if (t < 8) {
        int sv = ws[t];
        int tt = sv;
#pragma unroll
        for (int o = 1; o < 8; o <<= 1) {
            int y = __shfl_up_sync(0xFFu, tt, o);
            if (t >= o) tt += y;
        }
        ws[t] = tt - sv;
    }
    __syncthreads();
    if (i < N_NODES) {
        int ex = x - v + ws[t >> 5] + boff[blockIdx.x];
        row_start[i] = ex;
        cursor[i] = ex;
    }
}
__global__ void scatter_edges(const int* __restrict__ src, const int* __restrict__ dst,
                              const float* __restrict__ ew, int* __restrict__ cursor,
                              int* __restrict__ ssrc, float* __restrict__ sew) {
    int e = blockIdx.x * blockDim.x + threadIdx.x;
    if (e >= N_EDGES) return;
    int d = dst[e];
    int p = atomicAdd(&cursor[d], 1);
    ssrc[p] = src[e];
    sew[p] = ew[e];
}

// ---------------- CSR aggregation: agg[v] = sum_{e in row v} w_e * Yn[src_e] ----------------
template <int C>
__global__ void __launch_bounds__(256) csr_agg(
    const int* __restrict__ row_start, const int* __restrict__ ssrc,
    const float* __restrict__ sew, const float* __restrict__ Yn, float* __restrict__ agg)
{
    int node = (blockIdx.x * blockDim.x + threadIdx.x) >> 5;
    if (node >= N_NODES) return;
    int lane = threadIdx.x & 31;
    int p0 = row_start[node], p1 = row_start[node + 1];
    float4 acc[C / 128];
#pragma unroll
    for (int c = 0; c < C / 128; c++) acc[c] = make_float4(0.f, 0.f, 0.f, 0.f);

    int p = p0;
    for (; p + 1 < p1; p += 2) {
        int s0 = __ldg(&ssrc[p]),     s1 = __ldg(&ssrc[p + 1]);
        float w0 = __ldg(&sew[p]),    w1 = __ldg(&sew[p + 1]);
        const float4* y0 = (const float4*)(Yn + (size_t)s0 * C);
        const float4* y1 = (const float4*)(Yn + (size_t)s1 * C);
#pragma unroll
        for (int c = 0; c < C / 128; c++) {
            float4 v0 = __ldg(&y0[c * 32 + lane]);
            float4 v1 = __ldg(&y1[c * 32 + lane]);
            acc[c].x += w0 * v0.x + w1 * v1.x;
            acc[c].y += w0 * v0.y + w1 * v1.y;
            acc[c].z += w0 * v0.z + w1 * v1.z;
            acc[c].w += w0 * v0.w + w1 * v1.w;
        }
    }
    if (p < p1) {
        int s0 = __ldg(&ssrc[p]);
        float w0 = __ldg(&sew[p]);
        const float4* y0 = (const float4*)(Yn + (size_t)s0 * C);
#pragma unroll
        for (int c = 0; c < C / 128; c++) {
            float4 v0 = __ldg(&y0[c * 32 + lane]);
            acc[c].x += w0 * v0.x; acc[c].y += w0 * v0.y;
            acc[c].z += w0 * v0.z; acc[c].w += w0 * v0.w;
        }
    }
    float4* ap = (float4*)(agg + (size_t)node * C);
#pragma unroll
    for (int c = 0; c < C / 128; c++) ap[c * 32 + lane] = acc[c];
}

// ---------------- weight transpose (RNA tf32 round) ----------------
__global__ void transpose_w(const float* __restrict__ Ws, const float* __restrict__ Wn,
                            float* __restrict__ WT) {
    int mat = blockIdx.y;
    int l = mat / 6, sn = (mat / 3) & 1, g = mat % 3;
    const float* src = (sn ? Wn : Ws) + ((size_t)l * 3 + g) * GSZ;
    float* dst = WT + (size_t)mat * GSZ;
    int i = blockIdx.x * blockDim.x + threadIdx.x;
    if (i < GSZ) {
        int n = i >> 8; int k = i & 255;
        uint32_t t = to_tf32(src[k * 128 + n]);
        dst[i] = __uint_as_float(t);
    }
}

// ---------------- tensor-core GEMM via mma.sync tf32 ----------------
// A operand fed as raw f32 (HW uses tf32 bits -> RZ rounding); B pre-rounded RNA.
#define TSTR 36
#define TILE_B (128 * TSTR * 4)

__global__ void __launch_bounds__(256) gemm_tc(
    const float* __restrict__ A0, const float* __restrict__ A1,
    const float* __restrict__ BTself, const float* __restrict__ BTneigh,
    int half, float* __restrict__ Cself, float* __restrict__ Cneigh, int ldc)
{
    extern __shared__ float smem[];
    float* sA[2] = { smem,                smem + 128 * TSTR };
    float* sB[2] = { smem + 2 * 128 * TSTR, smem + 3 * 128 * TSTR };
    uint32_t uA[2] = { smem_u32(sA[0]), smem_u32(sA[1]) };
    uint32_t uB[2] = { smem_u32(sB[0]), smem_u32(sB[1]) };

    int tid = threadIdx.x, wid = tid >> 5, lid = tid & 31;
    int lr = lid >> 2, lc = lid & 3;
    int m0 = blockIdx.x * 128;
    int by = blockIdx.y;
    const float* BT; float* Cp; int colOff;
    if (by < half) { BT = BTself + (size_t)by * GSZ;           Cp = Cself;  colOff = by * 128; }
    else           { BT = BTneigh + (size_t)(by - half) * GSZ; Cp = Cneigh; colOff = (by - half) * 128; }

    int wm = wid & 1, wn = wid >> 1;

    float acc[4][4][4];
#pragma unroll
    for (int mt = 0; mt < 4; mt++)
#pragma unroll
        for (int nt = 0; nt < 4; nt++)
#pragma unroll
            for (int j = 0; j < 4; j++) acc[mt][nt][j] = 0.f;

    auto copy_tile = [&](int kt, int b) {
        const float* A = (kt < 4) ? A0 : A1;
        int kb = (kt & 3) * 32;
#pragma unroll
        for (int i = 0; i < 4; i++) {
            int c = tid + i * 256;
            int row = c >> 3, q = c & 7;
            int gr = m0 + row;
            int sz = (gr < N_NODES) ? 16 : 0;
            cp16(uA[b] + (uint32_t)(row * TSTR + q * 4) * 4,
                 A + (size_t)gr * 128 + kb + q * 4, sz);
            cp16(uB[b] + (uint32_t)(row * TSTR + q * 4) * 4,
                 BT + (size_t)row * 256 + kt * 32 + q * 4, 16);
        }
    };

    copy_tile(0, 0);
    CP_COMMIT();

    for (int kt = 0; kt < 8; kt++) {
        int b = kt & 1;
        if (kt < 7) { copy_tile(kt + 1, b ^ 1); CP_COMMIT(); CP_WAIT(1); }
        else        { CP_WAIT(0); }
        __syncthreads();

        const float* As = sA[b];
        const float* Bs = sB[b];
#pragma unroll
        for (int k8 = 0; k8 < 4; k8++) {
            int k0 = k8 * 8;
            uint32_t bf[4][2];
#pragma unroll
            for (int nt = 0; nt < 4; nt++) {
                int nb = 32 * wn + 8 * nt + lr;
                bf[nt][0] = __float_as_uint(Bs[nb * TSTR + k0 + lc]);
                bf[nt][1] = __float_as_uint(Bs[nb * TSTR + k0 + lc + 4]);
            }
#pragma unroll
            for (int mt = 0; mt < 4; mt++) {
                int rb = 64 * wm + 16 * mt;
                uint32_t a0 = __float_as_uint(As[(rb + lr) * TSTR + k0 + lc]);
                uint32_t a1 = __float_as_uint(As[(rb + 8 + lr) * TSTR + k0 + lc]);
                uint32_t a2 = __float_as_uint(As[(rb + lr) * TSTR + k0 + lc + 4]);
                uint32_t a3 = __float_as_uint(As[(rb + 8 + lr) * TSTR + k0 + lc + 4]);
#pragma unroll
                for (int nt = 0; nt < 4; nt++)
                    mma_tf32(acc[mt][nt][0], acc[mt][nt][1], acc[mt][nt][2], acc[mt][nt][3],
                             a0, a1, a2, a3, bf[nt][0], bf[nt][1]);
            }
        }
        __syncthreads();
    }

#pragma unroll
    for (int mt = 0; mt < 4; mt++) {
        int r0 = m0 + 64 * wm + 16 * mt + lr;
#pragma unroll
        for (int nt = 0; nt < 4; nt++) {
            int col = colOff + 32 * wn + 8 * nt + 2 * lc;
            if (r0 < N_NODES)
                *(float2*)(Cp + (size_t)r0 * ldc + col) =
                    make_float2(acc[mt][nt][0], acc[mt][nt][1]);
            if (r0 + 8 < N_NODES)
                *(float2*)(Cp + (size_t)(r0 + 8) * ldc + col) =
                    make_float2(acc[mt][nt][2], acc[mt][nt][3]);
        }
    }
}

// ---------------- gates ----------------
__global__ void gates_ru(const float* __restrict__ S1, const float* __restrict__ A1g,
                         const float* __restrict__ br, const float* __restrict__ bu,
                         const float* __restrict__ h,
                         float* __restrict__ RH, float* __restrict__ U)
{
    int idx = blockIdx.x * blockDim.x + threadIdx.x;
    if (idx >= NF) return;
    int i = idx >> 7;
    int f = idx & 127;
    float r = sigmoidf_(S1[(size_t)i * 256 + f] + A1g[(size_t)i * 256 + f] + __ldg(&br[f]));
    float u = sigmoidf_(S1[(size_t)i * 256 + 128 + f] + A1g[(size_t)i * 256 + 128 + f] + __ldg(&bu[f]));
    RH[idx] = r * h[idx];
    U[idx] = u;
}

__global__ void finalize(const float* __restrict__ S2, const float* __restrict__ A2g,
                         const float* __restrict__ bc,
                         const float* __restrict__ h, const float* __restrict__ U,
                         float* __restrict__ out_layer, float* __restrict__ out_extra)
{
    int idx = blockIdx.x * blockDim.x + threadIdx.x;
    if (idx >= NF) return;
    int f = idx & 127;
    float c = sigmoidf_(S2[idx] + A2g[idx] + __ldg(&bc[f]));
    float u = U[idx];
    float hn = u * h[idx] + (1.0f - u) * c;
    out_layer[idx] = hn;
    if (out_extra) out_extra[idx] = hn;
}

// ---------------- launch ----------------
extern "C" void kernel_launch(void* const* d_in, const int* in_sizes, int n_in,
                              void* d_out, int out_size)
{
    const float* x0   = (const float*)d_in[0];
    const float* hst  = (const float*)d_in[1];
    const int*   src  = (const int*)d_in[2];
    const int*   dst  = (const int*)d_in[3];
    const float* ew   = (const float*)d_in[4];
    const float* Ws   = (const float*)d_in[5];
    const float* Wn   = (const float*)d_in[6];
    const float* bias = (const float*)d_in[7];
    float* out = (float*)d_out;

    float *S1, *Yn1, *A1g, *S2, *Yn2, *A2g, *RH, *U, *WT, *SEW;
    int *DEG, *RS, *CUR, *SSRC, *BSUM, *BOFF;
    cudaGetSymbolAddress((void**)&S1,  g_S1);
    cudaGetSymbolAddress((void**)&Yn1, g_Yn1);
    cudaGetSymbolAddress((void**)&A1g, g_AGG1);
    cudaGetSymbolAddress((void**)&S2,  g_S2);
    cudaGetSymbolAddress((void**)&Yn2, g_Yn2);
    cudaGetSymbolAddress((void**)&A2g, g_AGG2);
    cudaGetSymbolAddress((void**)&RH,  g_RH);
    cudaGetSymbolAddress((void**)&U,   g_U);
    cudaGetSymbolAddress((void**)&WT,  g_WT);
    cudaGetSymbolAddress((void**)&DEG, g_deg);
    cudaGetSymbolAddress((void**)&RS,  g_rowstart);
    cudaGetSymbolAddress((void**)&CUR, g_cursor);
    cudaGetSymbolAddress((void**)&SSRC, g_ssrc);
    cudaGetSymbolAddress((void**)&SEW, g_sew);
    cudaGetSymbolAddress((void**)&BSUM, g_bsum);
    cudaGetSymbolAddress((void**)&BOFF, g_boff);

    const int SMEM_SZ = 4 * TILE_B;
    cudaFuncSetAttribute(gemm_tc, cudaFuncAttributeMaxDynamicSharedMemorySize, SMEM_SZ);

    const int mtiles = (N_NODES + 127) / 128;
    const int agg_blocks = (N_NODES * 32 + 255) / 256;
    const int el_blocks = (NF + 255) / 256;
    const int eb = (N_EDGES + 255) / 256;

    // ---- CSR build (parallel scan) + weight transpose ----
    transpose_w<<<dim3((GSZ + 255) / 256, 12), 256>>>(Ws, Wn, WT);
    zero_int<<<(N_NODES + 255) / 256, 256>>>(DEG, N_NODES);
    hist_dst<<<eb, 256>>>(dst, DEG);
    scan_bsum<<<SCAN_B, 256>>>(DEG, BSUM);
    scan_boff<<<1, 256>>>(BSUM, BOFF, RS);
    scan_apply<<<SCAN_B, 256>>>(DEG, BOFF, RS, CUR);
    scatter_edges<<<eb, 256>>>(src, dst, ew, CUR, SSRC, SEW);

    for (int l = 0; l < 2; l++) {
        const float* xl = (l == 0) ? x0 : (out + NF);
        const float* hl = hst + (size_t)l * NF;
        const float* BTs = WT + (size_t)((l * 2 + 0) * 3) * GSZ;
        const float* BTn = WT + (size_t)((l * 2 + 1) * 3) * GSZ;
        const float* b_r = bias + ((size_t)l * 3 + 0) * 128;
        const float* b_u = bias + ((size_t)l * 3 + 1) * 128;
        const float* b_c = bias + ((size_t)l * 3 + 2) * 128;

        gemm_tc<<<dim3(mtiles, 4), 256, SMEM_SZ>>>(xl, hl, BTs, BTn, 2, S1, Yn1, 256);
        csr_agg<256><<<agg_blocks, 256>>>(RS, SSRC, SEW, Yn1, A1g);
        gates_ru<<<el_blocks, 256>>>(S1, A1g, b_r, b_u, hl, RH, U);

        gemm_tc<<<dim3(mtiles, 2), 256, SMEM_SZ>>>(xl, RH, BTs + 2 * GSZ, BTn + 2 * GSZ,
                                                   1, S2, Yn2, 128);
        csr_agg<128><<<agg_blocks, 256>>>(RS, SSRC, SEW, Yn2, A2g);

        float* out_layer = out + (size_t)(l + 1) * NF;
        float* out_extra = (l == 1) ? out : nullptr;
        finalize<<<el_blocks, 256>>>(S2, A2g, b_c, hl, U, out_layer, out_extra);
    }
    (void)in_sizes; (void)n_in; (void)out_size;
}

// round 13
// speedup vs baseline: 1.9685x; 1.3311x over previous
#include <cuda_runtime.h>
#include <cuda_bf16.h>
#include <math.h>
#include <stdint.h>

#define N_NODES 50000
#define N_EDGES 800000
#define F 128
#define NF (N_NODES * F)
#define GSZ (256 * 128)   // one gate weight matrix [2F, F]
#define SCAN_B 196        // ceil(50000/256)

// ---------------- static device scratch (no allocs allowed) ----------------
__device__ float g_S1[N_NODES * 256];
__device__ __nv_bfloat16 g_Yn1[N_NODES * 256];
__device__ float g_S2[N_NODES * 128];
__device__ __nv_bfloat16 g_Yn2[N_NODES * 128];
__device__ float g_RH[N_NODES * 128];
__device__ float g_U[N_NODES * 128];
__device__ float g_WT[12 * GSZ];        // transposed tf32-rounded weights [128n x 256k]
// CSR scratch
__device__ int   g_deg[N_NODES];
__device__ int   g_rowstart[N_NODES + 1];
__device__ int   g_cursor[N_NODES];
__device__ int   g_ssrc[N_EDGES];
__device__ float g_sew[N_EDGES];
__device__ int   g_bsum[SCAN_B];
__device__ int   g_boff[SCAN_B];

// ---------------- helpers ----------------
__device__ __forceinline__ float sigmoidf_(float x) { return 1.0f / (1.0f + expf(-x)); }

__device__ __forceinline__ uint32_t smem_u32(const void* p) {
    uint32_t a;
    asm("{ .reg .u64 t; cvta.to.shared.u64 t, %1; cvt.u32.u64 %0, t; }" : "=r"(a) : "l"(p));
    return a;
}
__device__ __forceinline__ uint32_t to_tf32(float x) {
    uint32_t r;
    asm("cvt.rna.tf32.f32 %0, %1;" : "=r"(r) : "f"(x));
    return r;
}
__device__ __forceinline__ void cp16(uint32_t dst, const void* src, int srcsz) {
    asm volatile("cp.async.cg.shared.global [%0], [%1], 16, %2;"
                 :: "r"(dst), "l"(src), "r"(srcsz) : "memory");
}
#define CP_COMMIT() asm volatile("cp.async.commit_group;" ::: "memory")
#define CP_WAIT(n)  asm volatile("cp.async.wait_group %0;" :: "n"(n) : "memory")

__device__ __forceinline__ void mma_tf32(float& d0, float& d1, float& d2, float& d3,
                                         uint32_t a0, uint32_t a1, uint32_t a2, uint32_t a3,
                                         uint32_t b0, uint32_t b1) {
    asm volatile("mma.sync.aligned.m16n8k8.row.col.f32.tf32.tf32.f32 "
                 "{%0,%1,%2,%3}, {%4,%5,%6,%7}, {%8,%9}, {%0,%1,%2,%3};"
                 : "+f"(d0), "+f"(d1), "+f"(d2), "+f"(d3)
                 : "r"(a0), "r"(a1), "r"(a2), "r"(a3), "r"(b0), "r"(b1));
}

// unpack 8 bf16 (uint4) and fma into acc[8]
__device__ __forceinline__ void acc8_bf16(float* a, uint4 v, float w) {
    float2 f0 = __bfloat1622float2(*(__nv_bfloat162*)&v.x);
    float2 f1 = __bfloat1622float2(*(__nv_bfloat162*)&v.y);
    float2 f2 = __bfloat1622float2(*(__nv_bfloat162*)&v.z);
    float2 f3 = __bfloat1622float2(*(__nv_bfloat162*)&v.w);
    a[0] += w * f0.x; a[1] += w * f0.y;
    a[2] += w * f1.x; a[3] += w * f1.y;
    a[4] += w * f2.x; a[5] += w * f2.y;
    a[6] += w * f3.x; a[7] += w * f3.y;
}
__device__ __forceinline__ void acc4_bf16(float* a, uint2 v, float w) {
    float2 f0 = __bfloat1622float2(*(__nv_bfloat162*)&v.x);
    float2 f1 = __bfloat1622float2(*(__nv_bfloat162*)&v.y);
    a[0] += w * f0.x; a[1] += w * f0.y;
    a[2] += w * f1.x; a[3] += w * f1.y;
}

// ---------------- CSR build ----------------
__global__ void zero_int(int* __restrict__ p, int n) {
    int i = blockIdx.x * blockDim.x + threadIdx.x;
    if (i < n) p[i] = 0;
}
__global__ void hist_dst(const int* __restrict__ dst, int* __restrict__ deg) {
    int e = blockIdx.x * blockDim.x + threadIdx.x;
    if (e < N_EDGES) atomicAdd(&deg[dst[e]], 1);
}
__global__ void scan_bsum(const int* __restrict__ deg, int* __restrict__ bsum) {
    __shared__ int ws[8];
    int i = blockIdx.x * 256 + threadIdx.x;
    int v = (i < N_NODES) ? deg[i] : 0;
#pragma unroll
    for (int o = 16; o > 0; o >>= 1) v += __shfl_down_sync(0xFFFFFFFFu, v, o);
    if ((threadIdx.x & 31) == 0) ws[threadIdx.x >> 5] = v;
    __syncthreads();
    if (threadIdx.x < 8) {
        int s = ws[threadIdx.x];
#pragma unroll
        for (int o = 4; o > 0; o >>= 1) s += __shfl_down_sync(0xFFu, s, o);
        if (threadIdx.x == 0) bsum[blockIdx.x] = s;
    }
}
__global__ void scan_boff(const int* __restrict__ bsum, int* __restrict__ boff,
                          int* __restrict__ row_start) {
    __shared__ int s[256];
    int t = threadIdx.x;
    int v = (t < SCAN_B) ? bsum[t] : 0;
    s[t] = v;
    __syncthreads();
#pragma unroll
    for (int o = 1; o < 256; o <<= 1) {
        int y = (t >= o) ? s[t - o] : 0;
        __syncthreads();
        s[t] += y;
        __syncthreads();
    }
    if (t < SCAN_B) boff[t] = s[t] - v;
    if (t == 255) row_start[N_NODES] = s[255];
}
__global__ void scan_apply(const int* __restrict__ deg, const int* __restrict__ boff,
                           int* __restrict__ row_start, int* __restrict__ cursor) {
    __shared__ int ws[8];
    int t = threadIdx.x;
    int i = blockIdx.x * 256 + t;
    int v = (i < N_NODES) ? deg[i] : 0;
    int x = v;
#pragma unroll
    for (int o = 1; o < 32; o <<= 1) {
        int y = __shfl_up_sync(0xFFFFFFFFu, x, o);
        if ((t & 31) >= o) x += y;
    }
    if ((t & 31) == 31) ws[t >> 5] = x;
    __syncthreads();
    if (t < 8) {
        int sv = ws[t];
        int tt = sv;
#pragma unroll
        for (int o = 1; o < 8; o <<= 1) {
            int y = __shfl_up_sync(0xFFu, tt, o);
            if (t >= o) tt += y;
        }
        ws[t] = tt - sv;
    }
    __syncthreads();
    if (i < N_NODES) {
        int ex = x - v + ws[t >> 5] + boff[blockIdx.x];
        row_start[i] = ex;
        cursor[i] = ex;
    }
}
__global__ void scatter_edges(const int* __restrict__ src, const int* __restrict__ dst,
                              const float* __restrict__ ew, int* __restrict__ cursor,
                              int* __restrict__ ssrc, float* __restrict__ sew) {
    int e = blockIdx.x * blockDim.x + threadIdx.x;
    if (e >= N_EDGES) return;
    int d = dst[e];
    int p = atomicAdd(&cursor[d], 1);
    ssrc[p] = src[e];
    sew[p] = ew[e];
}

// ---------------- fused agg + gates r,u (stage 1) ----------------
// warp per node: agg = sum w_e*Yn1[src_e] (bf16 gather, fp32 acc), then
// r=sig(S1+agg+b_r), u=sig(S1+agg+b_u); RH=r*h (lanes 0-15), U=u (lanes 16-31)
__global__ void __launch_bounds__(256) csr_agg_ru(
    const int* __restrict__ rs, const int* __restrict__ ssrc,
    const float* __restrict__ sew, const __nv_bfloat16* __restrict__ Yn,
    const float* __restrict__ S1, const float* __restrict__ bias_ru,
    const float* __restrict__ h, float* __restrict__ RH, float* __restrict__ U)
{
    int node = (blockIdx.x * blockDim.x + threadIdx.x) >> 5;
    if (node >= N_NODES) return;
    int lane = threadIdx.x & 31;
    int p0 = rs[node], p1 = rs[node + 1];
    float acc[8];
#pragma unroll
    for (int j = 0; j < 8; j++) acc[j] = 0.f;

    int p = p0;
    for (; p + 1 < p1; p += 2) {
        int s0 = __ldg(&ssrc[p]),  s1 = __ldg(&ssrc[p + 1]);
        float w0 = __ldg(&sew[p]), w1 = __ldg(&sew[p + 1]);
        uint4 v0 = __ldg((const uint4*)(Yn + (size_t)s0 * 256) + lane);
        uint4 v1 = __ldg((const uint4*)(Yn + (size_t)s1 * 256) + lane);
        acc8_bf16(acc, v0, w0);
        acc8_bf16(acc, v1, w1);
    }
    if (p < p1) {
        int s0 = __ldg(&ssrc[p]);
        float w0 = __ldg(&sew[p]);
        uint4 v0 = __ldg((const uint4*)(Yn + (size_t)s0 * 256) + lane);
        acc8_bf16(acc, v0, w0);
    }

    int col = lane * 8;     // column in the 256-wide [r|u] plane
    const float4* sp = (const float4*)(S1 + (size_t)node * 256 + col);
    float4 sa = sp[0], sb = sp[1];
    float4 ba = __ldg((const float4*)(bias_ru + col));
    float4 bb = __ldg((const float4*)(bias_ru + col) + 1);
    float g0 = sigmoidf_(sa.x + acc[0] + ba.x);
    float g1 = sigmoidf_(sa.y + acc[1] + ba.y);
    float g2 = sigmoidf_(sa.z + acc[2] + ba.z);
    float g3 = sigmoidf_(sa.w + acc[3] + ba.w);
    float g4 = sigmoidf_(sb.x + acc[4] + bb.x);
    float g5 = sigmoidf_(sb.y + acc[5] + bb.y);
    float g6 = sigmoidf_(sb.z + acc[6] + bb.z);
    float g7 = sigmoidf_(sb.w + acc[7] + bb.w);

    int f = (lane & 15) * 8;
    if (lane < 16) {   // r-half: RH = r * h
        const float4* hp = (const float4*)(h + (size_t)node * 128 + f);
        float4 h0 = hp[0], h1 = hp[1];
        float4* op = (float4*)(RH + (size_t)node * 128 + f);
        op[0] = make_float4(g0 * h0.x, g1 * h0.y, g2 * h0.z, g3 * h0.w);
        op[1] = make_float4(g4 * h1.x, g5 * h1.y, g6 * h1.z, g7 * h1.w);
    } else {           // u-half
        float4* op = (float4*)(U + (size_t)node * 128 + f);
        op[0] = make_float4(g0, g1, g2, g3);
        op[1] = make_float4(g4, g5, g6, g7);
    }
}

// ---------------- fused agg + finalize (stage 2) ----------------
// c=sig(S2+agg+b_c); h' = u*h + (1-u)*c
__global__ void __launch_bounds__(256) csr_agg_fin(
    const int* __restrict__ rs, const int* __restrict__ ssrc,
    const float* __restrict__ sew, const __nv_bfloat16* __restrict__ Yn,
    const float* __restrict__ S2, const float* __restrict__ bc,
    const float* __restrict__ h, const float* __restrict__ U,
    float* __restrict__ out_layer, float* __restrict__ out_extra)
{
    int node = (blockIdx.x * blockDim.x + threadIdx.x) >> 5;
    if (node >= N_NODES) return;
    int lane = threadIdx.x & 31;
    int p0 = rs[node], p1 = rs[node + 1];
    float acc[4];
#pragma unroll
    for (int j = 0; j < 4; j++) acc[j] = 0.f;

    int p = p0;
    for (; p + 1 < p1; p += 2) {
        int s0 = __ldg(&ssrc[p]),  s1 = __ldg(&ssrc[p + 1]);
        float w0 = __ldg(&sew[p]), w1 = __ldg(&sew[p + 1]);
        uint2 v0 = __ldg((const uint2*)(Yn + (size_t)s0 * 128) + lane);
        uint2 v1 = __ldg((const uint2*)(Yn + (size_t)s1 * 128) + lane);
        acc4_bf16(acc, v0, w0);
        acc4_bf16(acc, v1, w1);
    }
    if (p < p1) {
        int s0 = __ldg(&ssrc[p]);
        float w0 = __ldg(&sew[p]);
        uint2 v0 = __ldg((const uint2*)(Yn + (size_t)s0 * 128) + lane);
        acc4_bf16(acc, v0, w0);
    }

    int f = lane * 4;
    float4 s = *(const float4*)(S2 + (size_t)node * 128 + f);
    float4 b = __ldg((const float4*)(bc + f));
    float4 u = *(const float4*)(U + (size_t)node * 128 + f);
    float4 hh = *(const float4*)(h + (size_t)node * 128 + f);
    float c0 = sigmoidf_(s.x + acc[0] + b.x);
    float c1 = sigmoidf_(s.y + acc[1] + b.y);
    float c2 = sigmoidf_(s.z + acc[2] + b.z);
    float c3 = sigmoidf_(s.w + acc[3] + b.w);
    float4 hn = make_float4(u.x * hh.x + (1.f - u.x) * c0,
                            u.y * hh.y + (1.f - u.y) * c1,
                            u.z * hh.z + (1.f - u.z) * c2,
                            u.w * hh.w + (1.f - u.w) * c3);
    *(float4*)(out_layer + (size_t)node * 128 + f) = hn;
    if (out_extra) *(float4*)(out_extra + (size_t)node * 128 + f) = hn;
}

// ---------------- weight transpose (RNA tf32 round) ----------------
__global__ void transpose_w(const float* __restrict__ Ws, const float* __restrict__ Wn,
                            float* __restrict__ WT) {
    int mat = blockIdx.y;
    int l = mat / 6, sn = (mat / 3) & 1, g = mat % 3;
    const float* src = (sn ? Wn : Ws) + ((size_t)l * 3 + g) * GSZ;
    float* dst = WT + (size_t)mat * GSZ;
    int i = blockIdx.x * blockDim.x + threadIdx.x;
    if (i < GSZ) {
        int n = i >> 8; int k = i & 255;
        uint32_t t = to_tf32(src[k * 128 + n]);
        dst[i] = __uint_as_float(t);
    }
}

// ---------------- tensor-core GEMM via mma.sync tf32 ----------------
// self output: fp32; neighbor output: bf16 (for cheap gathers downstream)
#define TSTR 36
#define TILE_B (128 * TSTR * 4)

__global__ void __launch_bounds__(256) gemm_tc(
    const float* __restrict__ A0, const float* __restrict__ A1,
    const float* __restrict__ BTself, const float* __restrict__ BTneigh,
    int half, float* __restrict__ Cself, __nv_bfloat16* __restrict__ Cneigh, int ldc)
{
    extern __shared__ float smem[];
    float* sA[2] = { smem,                smem + 128 * TSTR };
    float* sB[2] = { smem + 2 * 128 * TSTR, smem + 3 * 128 * TSTR };
    uint32_t uA[2] = { smem_u32(sA[0]), smem_u32(sA[1]) };
    uint32_t uB[2] = { smem_u32(sB[0]), smem_u32(sB[1]) };

    int tid = threadIdx.x, wid = tid >> 5, lid = tid & 31;
    int lr = lid >> 2, lc = lid & 3;
    int m0 = blockIdx.x * 128;
    int by = blockIdx.y;
    bool is_self = (by < half);
    const float* BT;
    int colOff;
    if (is_self) { BT = BTself + (size_t)by * GSZ;           colOff = by * 128; }
    else         { BT = BTneigh + (size_t)(by - half) * GSZ; colOff = (by - half) * 128; }

    int wm = wid & 1, wn = wid >> 1;

    float acc[4][4][4];
#pragma unroll
    for (int mt = 0; mt < 4; mt++)
#pragma unroll
        for (int nt = 0; nt < 4; nt++)
#pragma unroll
            for (int j = 0; j < 4; j++) acc[mt][nt][j] = 0.f;

    auto copy_tile = [&](int kt, int b) {
        const float* A = (kt < 4) ? A0 : A1;
        int kb = (kt & 3) * 32;
#pragma unroll
        for (int i = 0; i < 4; i++) {
            int c = tid + i * 256;
            int row = c >> 3, q = c & 7;
            int gr = m0 + row;
            int sz = (gr < N_NODES) ? 16 : 0;
            cp16(uA[b] + (uint32_t)(row * TSTR + q * 4) * 4,
                 A + (size_t)gr * 128 + kb + q * 4, sz);
            cp16(uB[b] + (uint32_t)(row * TSTR + q * 4) * 4,
                 BT + (size_t)row * 256 + kt * 32 + q * 4, 16);
        }
    };

    copy_tile(0, 0);
    CP_COMMIT();

    for (int kt = 0; kt < 8; kt++) {
        int b = kt & 1;
        if (kt < 7) { copy_tile(kt + 1, b ^ 1); CP_COMMIT(); CP_WAIT(1); }
        else        { CP_WAIT(0); }
        __syncthreads();

        const float* As = sA[b];
        const float* Bs = sB[b];
#pragma unroll
        for (int k8 = 0; k8 < 4; k8++) {
            int k0 = k8 * 8;
            uint32_t bf[4][2];
#pragma unroll
            for (int nt = 0; nt < 4; nt++) {
                int nb = 32 * wn + 8 * nt + lr;
                bf[nt][0] = __float_as_uint(Bs[nb * TSTR + k0 + lc]);
                bf[nt][1] = __float_as_uint(Bs[nb * TSTR + k0 + lc + 4]);
            }
#pragma unroll
            for (int mt = 0; mt < 4; mt++) {
                int rb = 64 * wm + 16 * mt;
                uint32_t a0 = __float_as_uint(As[(rb + lr) * TSTR + k0 + lc]);
                uint32_t a1 = __float_as_uint(As[(rb + 8 + lr) * TSTR + k0 + lc]);
                uint32_t a2 = __float_as_uint(As[(rb + lr) * TSTR + k0 + lc + 4]);
                uint32_t a3 = __float_as_uint(As[(rb + 8 + lr) * TSTR + k0 + lc + 4]);
#pragma unroll
                for (int nt = 0; nt < 4; nt++)
                    mma_tf32(acc[mt][nt][0], acc[mt][nt][1], acc[mt][nt][2], acc[mt][nt][3],
                             a0, a1, a2, a3, bf[nt][0], bf[nt][1]);
            }
        }
        __syncthreads();
    }

#pragma unroll
    for (int mt = 0; mt < 4; mt++) {
        int r0 = m0 + 64 * wm + 16 * mt + lr;
#pragma unroll
        for (int nt = 0; nt < 4; nt++) {
            int col = colOff + 32 * wn + 8 * nt + 2 * lc;
            if (is_self) {
                if (r0 < N_NODES)
                    *(float2*)(Cself + (size_t)r0 * ldc + col) =
                        make_float2(acc[mt][nt][0], acc[mt][nt][1]);
                if (r0 + 8 < N_NODES)
                    *(float2*)(Cself + (size_t)(r0 + 8) * ldc + col) =
                        make_float2(acc[mt][nt][2], acc[mt][nt][3]);
            } else {
                if (r0 < N_NODES)
                    *(__nv_bfloat162*)(Cneigh + (size_t)r0 * ldc + col) =
                        __floats2bfloat162_rn(acc[mt][nt][0], acc[mt][nt][1]);
                if (r0 + 8 < N_NODES)
                    *(__nv_bfloat162*)(Cneigh + (size_t)(r0 + 8) * ldc + col) =
                        __floats2bfloat162_rn(acc[mt][nt][2], acc[mt][nt][3]);
            }
        }
    }
}

// ---------------- launch ----------------
extern "C" void kernel_launch(void* const* d_in, const int* in_sizes, int n_in,
                              void* d_out, int out_size)
{
    const float* x0   = (const float*)d_in[0];
    const float* hst  = (const float*)d_in[1];
    const int*   src  = (const int*)d_in[2];
    const int*   dst  = (const int*)d_in[3];
    const float* ew   = (const float*)d_in[4];
    const float* Ws   = (const float*)d_in[5];
    const float* Wn   = (const float*)d_in[6];
    const float* bias = (const float*)d_in[7];
    float* out = (float*)d_out;

    float *S1, *S2, *RH, *U, *WT, *SEW;
    __nv_bfloat16 *Yn1, *Yn2;
    int *DEG, *RS, *CUR, *SSRC, *BSUM, *BOFF;
    cudaGetSymbolAddress((void**)&S1,  g_S1);
    cudaGetSymbolAddress((void**)&Yn1, g_Yn1);
    cudaGetSymbolAddress((void**)&S2,  g_S2);
    cudaGetSymbolAddress((void**)&Yn2, g_Yn2);
    cudaGetSymbolAddress((void**)&RH,  g_RH);
    cudaGetSymbolAddress((void**)&U,   g_U);
    cudaGetSymbolAddress((void**)&WT,  g_WT);
    cudaGetSymbolAddress((void**)&DEG, g_deg);
    cudaGetSymbolAddress((void**)&RS,  g_rowstart);
    cudaGetSymbolAddress((void**)&CUR, g_cursor);
    cudaGetSymbolAddress((void**)&SSRC, g_ssrc);
    cudaGetSymbolAddress((void**)&SEW, g_sew);
    cudaGetSymbolAddress((void**)&BSUM, g_bsum);
    cudaGetSymbolAddress((void**)&BOFF, g_boff);

    const int SMEM_SZ = 4 * TILE_B;
    cudaFuncSetAttribute(gemm_tc, cudaFuncAttributeMaxDynamicSharedMemorySize, SMEM_SZ);

    const int mtiles = (N_NODES + 127) / 128;
    const int agg_blocks = (N_NODES * 32 + 255) / 256;
    const int eb = (N_EDGES + 255) / 256;

    // ---- CSR build (parallel scan) + weight transpose ----
    transpose_w<<<dim3((GSZ + 255) / 256, 12), 256>>>(Ws, Wn, WT);
    zero_int<<<(N_NODES + 255) / 256, 256>>>(DEG, N_NODES);
    hist_dst<<<eb, 256>>>(dst, DEG);
    scan_bsum<<<SCAN_B, 256>>>(DEG, BSUM);
    scan_boff<<<1, 256>>>(BSUM, BOFF, RS);
    scan_apply<<<SCAN_B, 256>>>(DEG, BOFF, RS, CUR);
    scatter_edges<<<eb, 256>>>(src, dst, ew, CUR, SSRC, SEW);

    for (int l = 0; l < 2; l++) {
        const float* xl = (l == 0) ? x0 : (out + NF);
        const float* hl = hst + (size_t)l * NF;
        const float* BTs = WT + (size_t)((l * 2 + 0) * 3) * GSZ;
        const float* BTn = WT + (size_t)((l * 2 + 1) * 3) * GSZ;
        const float* b_ru = bias + (size_t)l * 384;          // [b_r | b_u]
        const float* b_c  = bias + (size_t)l * 384 + 256;

        // stage 1: [S_r|S_u] fp32 and [Yn_r|Yn_u] bf16
        gemm_tc<<<dim3(mtiles, 4), 256, SMEM_SZ>>>(xl, hl, BTs, BTn, 2, S1, Yn1, 256);
        csr_agg_ru<<<agg_blocks, 256>>>(RS, SSRC, SEW, Yn1, S1, b_ru, hl, RH, U);

        // stage 2: S_c fp32, Yn_c bf16 with xh2 = [x, r*h]
        gemm_tc<<<dim3(mtiles, 2), 256, SMEM_SZ>>>(xl, RH, BTs + 2 * GSZ, BTn + 2 * GSZ,
                                                   1, S2, Yn2, 128);
        float* out_layer = out + (size_t)(l + 1) * NF;
        float* out_extra = (l == 1) ? out : nullptr;
        csr_agg_fin<<<agg_blocks, 256>>>(RS, SSRC, SEW, Yn2, S2, b_c, hl, U,
                                         out_layer, out_extra);
    }
    (void)in_sizes; (void)n_in; (void)out_size;
}